// round 12
// baseline (speedup 1.0000x reference)
#include <cuda_runtime.h>
#include <cuda_bf16.h>
#include <math_constants.h>
#include <stdint.h>

#define N_ROWS 65536
#define K_CODES 8192
#define D_DIM 256
#define CAP 64
#define MARGIN 4e-4f
#define S_E (1.0f / (8192.0f * 127.0f))
#define N_TILES (N_ROWS / 128)
#define GRID_PERSIST 296

// ---------------------------------------------------------------- scratch
__device__ float g_a[N_ROWS];
__device__ float g_c[K_CODES];
__device__ float g_coef[N_ROWS];                 // 2 * s_z[n] * s_e
__device__ double g_part[N_ROWS];
__device__ int8_t g_z8[(size_t)N_ROWS * D_DIM];  // 16 MB, ksp/quad packed
__device__ int8_t g_e8[(size_t)K_CODES * D_DIM]; // 2 MB, plain row-major
__device__ int g_cand[(size_t)N_ROWS * CAP];
__device__ int g_cnt[N_ROWS];
__device__ int g_tile_ctr;

__device__ __forceinline__ uint32_t smem_u32(const void* p) {
    uint32_t a;
    asm("{ .reg .u64 t; cvta.to.shared.u64 t, %1; cvt.u32.u64 %0, t; }" : "=r"(a) : "l"(p));
    return a;
}
__device__ __forceinline__ uint32_t q4pack(const float* p, float inv) {
    uint32_t r = 0;
    #pragma unroll
    for (int i = 0; i < 4; ++i) {
        int v = __float2int_rn(p[i] * inv);
        v = max(-127, min(127, v));
        r |= (uint32_t)(v & 0xff) << (8 * i);
    }
    return r;
}

// ---------------------------------------------------------------- z: norms + per-row int8 quant
// One row per thread, d-chunks of 32 staged via smem. Per-row reduction is
// STRICTLY sequential fadd(fmul) over ascending d (round-1 semantics).
__global__ void __launch_bounds__(256) norms_quant_z_kernel(const float* __restrict__ x,
                                                            int8_t* __restrict__ y) {
    __shared__ float s[256][33];
    int r0 = blockIdx.x * 256;
    int tid = threadIdx.x;
    float acc = 0.0f, amax = 0.0f;
    #pragma unroll 1
    for (int ch = 0; ch < 8; ++ch) {
        for (int i = tid; i < 2048; i += 256) {
            int row = i >> 3, c4 = i & 7;
            float4 v = ((const float4*)(x + (size_t)(r0 + row) * D_DIM + ch * 32))[c4];
            s[row][c4 * 4 + 0] = v.x; s[row][c4 * 4 + 1] = v.y;
            s[row][c4 * 4 + 2] = v.z; s[row][c4 * 4 + 3] = v.w;
        }
        __syncthreads();
        #pragma unroll
        for (int d = 0; d < 32; ++d) {
            float v = s[tid][d];
            acc = __fadd_rn(acc, __fmul_rn(v, v));
            amax = fmaxf(amax, fabsf(v));
        }
        __syncthreads();
    }
    g_a[r0 + tid] = acc;
    float inv = (amax > 0.0f) ? 127.0f / amax : 0.0f;
    g_coef[r0 + tid] = 2.0f * (amax / 127.0f) * S_E;
    // pass 2: quantize (re-stage; identical values)
    #pragma unroll 1
    for (int ch = 0; ch < 8; ++ch) {
        for (int i = tid; i < 2048; i += 256) {
            int row = i >> 3, c4 = i & 7;
            float4 v = ((const float4*)(x + (size_t)(r0 + row) * D_DIM + ch * 32))[c4];
            s[row][c4 * 4 + 0] = v.x; s[row][c4 * 4 + 1] = v.y;
            s[row][c4 * 4 + 2] = v.z; s[row][c4 * 4 + 3] = v.w;
        }
        __syncthreads();
        const float* rp = &s[tid][0];
        int8_t* base = y + (size_t)(r0 + tid) * D_DIM + (ch >> 1) * 64 + (ch & 1) * 8;
        #pragma unroll
        for (int q = 0; q < 4; ++q) {
            uint2 w;
            w.x = q4pack(rp + 4 * q, inv);
            w.y = q4pack(rp + 16 + 4 * q, inv);
            *(uint2*)(base + q * 16) = w;
        }
        __syncthreads();
    }
}

// ---------------------------------------------------------------- emb: norms + global-scale int8 quant (plain)
__global__ void __launch_bounds__(256) norms_quant_e_kernel(const float* __restrict__ x,
                                                            int8_t* __restrict__ y) {
    __shared__ float s[32][257];
    int r0 = blockIdx.x * 32;
    for (int i = threadIdx.x; i < 2048; i += 256) {
        int row = i >> 6, c4 = i & 63;
        float4 v = ((const float4*)(x + (size_t)(r0 + row) * D_DIM))[c4];
        s[row][c4 * 4 + 0] = v.x; s[row][c4 * 4 + 1] = v.y;
        s[row][c4 * 4 + 2] = v.z; s[row][c4 * 4 + 3] = v.w;
    }
    __syncthreads();
    if (threadIdx.x < 32) {
        int row = threadIdx.x;
        float acc = 0.0f;
        #pragma unroll 8
        for (int d = 0; d < D_DIM; ++d)
            acc = __fadd_rn(acc, __fmul_rn(s[row][d], s[row][d]));
        g_c[r0 + row] = acc;
    }
    __syncthreads();
    int row = threadIdx.x >> 3, blk = threadIdx.x & 7;
    const float inv = 8192.0f * 127.0f;
    const float* rp = &s[row][blk * 32];
    uint32_t w[8];
    #pragma unroll
    for (int j = 0; j < 8; ++j) w[j] = q4pack(rp + 4 * j, inv);
    uint4* dst = (uint4*)(y + (size_t)(r0 + row) * D_DIM + blk * 32);
    dst[0] = make_uint4(w[0], w[1], w[2], w[3]);
    dst[1] = make_uint4(w[4], w[5], w[6], w[7]);
}

// ---------------------------------------------------------------- int8 GEMM + shortlist (persistent)
#define ZS_STRIDE 320
#define ZS_BYTES (128 * ZS_STRIDE)            // 40960
#define ES_STRIDE 272
#define ES_BYTES (128 * ES_STRIDE)            // 34816
#define ES_OFF ZS_BYTES
#define PM_OFF (ES_OFF + 2 * ES_BYTES)        // 110592
#define AS_OFF (PM_OFF + 512)
#define CF_OFF (AS_OFF + 512)
#define TI_OFF (CF_OFF + 512)
#define SMEM_TOTAL (TI_OFF + 16)              // 112144 (2 CTAs/SM)

__global__ void __launch_bounds__(256, 2) vq_gemm_kernel() {
    extern __shared__ char smem[];
    const uint32_t sb = smem_u32(smem);
    float* pm_s = (float*)(smem + PM_OFF);
    float* a_s  = (float*)(smem + AS_OFF);
    float* cf_s = (float*)(smem + CF_OFF);
    int*   ti_s = (int*)(smem + TI_OFF);

    const int tid  = threadIdx.x;
    const int lane = tid & 31;
    const int wid  = tid >> 5;
    const int wm   = wid & 3;          // code-dim warp (4 x 32 codes)
    const int wn   = wid >> 2;         // row-dim warp  (2 x 64 rows)

    auto load_es = [&](int buf, int kt) {
        const int8_t* src = g_e8 + (size_t)kt * 128 * D_DIM;
        uint32_t dst = sb + ES_OFF + buf * ES_BYTES;
        #pragma unroll 4
        for (int i = tid; i < 2048; i += 256) {
            int code = i >> 4, ch = i & 15;
            uint32_t d = dst + (uint32_t)(code * ES_STRIDE + ch * 16);
            const void* s = src + (size_t)code * D_DIM + ch * 16;
            asm volatile("cp.async.cg.shared.global [%0], [%1], 16;" :: "r"(d), "l"(s) : "memory");
        }
        asm volatile("cp.async.commit_group;" ::: "memory");
    };

    #pragma unroll 1
    for (;;) {
        if (tid == 0) ti_s[0] = atomicAdd(&g_tile_ctr, 1);
        __syncthreads();                 // also fences prev tile's phase B vs reinit below
        const int tile = ti_s[0];
        if (tile >= N_TILES) break;
        const int n0 = tile * 128;

        // ---- stage z tile (int8) ----
        #pragma unroll 4
        for (int i = tid; i < 2048; i += 256) {
            int row = i >> 4, ch = i & 15;
            uint32_t d = sb + (uint32_t)(row * ZS_STRIDE + ch * 16);
            const void* s = g_z8 + (size_t)(n0 + row) * D_DIM + ch * 16;
            asm volatile("cp.async.cg.shared.global [%0], [%1], 16;" :: "r"(d), "l"(s) : "memory");
        }
        asm volatile("cp.async.commit_group;" ::: "memory");

        if (tid < 128) {
            pm_s[tid] = CUDART_INF_F;
            a_s[tid]  = __ldg(&g_a[n0 + tid]);
            cf_s[tid] = __ldg(&g_coef[n0 + tid]);
        }

        load_es(0, 0);
        asm volatile("cp.async.wait_group 0;" ::: "memory");
        __syncthreads();

        #pragma unroll 1
        for (int kt = 0; kt < 64; ++kt) {
            const int buf = kt & 1;
            if (kt + 1 < 64) load_es(buf ^ 1, kt + 1);

            const uint32_t es_base = sb + ES_OFF + buf * ES_BYTES;
            int acc[2][8][4];
            #pragma unroll
            for (int mf = 0; mf < 2; ++mf)
                #pragma unroll
                for (int nf = 0; nf < 8; ++nf)
                    #pragma unroll
                    for (int j = 0; j < 4; ++j) acc[mf][nf][j] = 0;

            #pragma unroll
            for (int ksp = 0; ksp < 4; ++ksp) {
                uint4 bv[8];
                #pragma unroll
                for (int nf = 0; nf < 8; ++nf)
                    bv[nf] = *(const uint4*)(smem +
                        (wn * 64 + nf * 8 + (lane >> 2)) * ZS_STRIDE +
                        ksp * 64 + (lane & 3) * 16);
                #pragma unroll
                for (int half = 0; half < 2; ++half) {
                    const int ks = ksp * 2 + half;
                    uint32_t a[2][4];
                    #pragma unroll
                    for (int mf = 0; mf < 2; ++mf) {
                        uint32_t addr = es_base +
                            (uint32_t)((wm * 32 + mf * 16 + (lane & 15)) * ES_STRIDE +
                                       ks * 32 + (lane >> 4) * 16);
                        asm volatile(
                            "ldmatrix.sync.aligned.m8n8.x4.shared.b16 {%0,%1,%2,%3}, [%4];"
                            : "=r"(a[mf][0]), "=r"(a[mf][1]), "=r"(a[mf][2]), "=r"(a[mf][3])
                            : "r"(addr));
                    }
                    #pragma unroll
                    for (int mf = 0; mf < 2; ++mf)
                        #pragma unroll
                        for (int nf = 0; nf < 8; ++nf) {
                            uint32_t bx = half ? bv[nf].z : bv[nf].x;
                            uint32_t by = half ? bv[nf].w : bv[nf].y;
                            asm volatile(
                                "mma.sync.aligned.m16n8k32.row.col.s32.s8.s8.s32 "
                                "{%0,%1,%2,%3}, {%4,%5,%6,%7}, {%8,%9}, {%0,%1,%2,%3};"
                                : "+r"(acc[mf][nf][0]), "+r"(acc[mf][nf][1]),
                                  "+r"(acc[mf][nf][2]), "+r"(acc[mf][nf][3])
                                : "r"(a[mf][0]), "r"(a[mf][1]), "r"(a[mf][2]), "r"(a[mf][3]),
                                  "r"(bx), "r"(by));
                        }
                }
            }

            // ---- epilogue A: dequant q, per-thread rowmins, guarded atomicMin ----
            float c0[2], c1[2];
            #pragma unroll
            for (int mf = 0; mf < 2; ++mf) {
                int m0 = kt * 128 + wm * 32 + mf * 16 + (lane >> 2);
                c0[mf] = __ldg(&g_c[m0]);
                c1[mf] = __ldg(&g_c[m0 + 8]);
            }
            float rowmin[8][2];
            #pragma unroll
            for (int nf = 0; nf < 8; ++nf)
                #pragma unroll
                for (int p = 0; p < 2; ++p) {
                    int nl = wn * 64 + nf * 8 + 2 * (lane & 3) + p;
                    float av = a_s[nl], cf = cf_s[nl];
                    float rm = CUDART_INF_F;
                    #pragma unroll
                    for (int mf = 0; mf < 2; ++mf)
                        #pragma unroll
                        for (int h = 0; h < 2; ++h) {
                            int j = 2 * h + p;
                            float f = (float)acc[mf][nf][j];      // exact (<2^24)
                            float q = __fadd_rn(__fmaf_rn(-cf, f, av), h ? c1[mf] : c0[mf]);
                            acc[mf][nf][j] = __float_as_int(q);
                            rm = fminf(rm, q);
                        }
                    rowmin[nf][p] = rm;
                }
            #pragma unroll
            for (int nf = 0; nf < 8; ++nf)
                #pragma unroll
                for (int p = 0; p < 2; ++p) {
                    int nl = wn * 64 + nf * 8 + 2 * (lane & 3) + p;
                    if (rowmin[nf][p] < pm_s[nl])                 // q > 0 always
                        atomicMin((int*)&pm_s[nl], __float_as_int(rowmin[nf][p]));
                }
            if (kt + 1 < 64)
                asm volatile("cp.async.wait_group 0;" ::: "memory");
            __syncthreads();   // pm visible + next es buffer ready
            // ---- phase B: append candidates (threshold pm_now+MARGIN always
            // admits the exact argmin and its ties; per-CTA state => set is
            // deterministic under any tile scheduling) ----
            #pragma unroll
            for (int nf = 0; nf < 8; ++nf)
                #pragma unroll
                for (int p = 0; p < 2; ++p) {
                    int nl = wn * 64 + nf * 8 + 2 * (lane & 3) + p;
                    float thr = pm_s[nl] + MARGIN;
                    if (rowmin[nf][p] <= thr) {
                        #pragma unroll
                        for (int mf = 0; mf < 2; ++mf)
                            #pragma unroll
                            for (int h = 0; h < 2; ++h)
                                if (__int_as_float(acc[mf][nf][2 * h + p]) <= thr) {
                                    int pos = atomicAdd(&g_cnt[n0 + nl], 1);
                                    if (pos < CAP)
                                        g_cand[(size_t)(n0 + nl) * CAP + pos] =
                                            kt * 128 + wm * 32 + mf * 16 + (lane >> 2) + h * 8;
                                }
                    }
                }
        }
    }
}

// ---------------------------------------------------------------- exact recheck + gather + loss
// Warp-per-row. Per-candidate dot keeps round-1 exact semantics: sequential
// fma over ascending d, q = fl(fl(a-fl(2M))+c). Winner = lexicographic (q,idx)
// min via packed u64 shuffle reduction (order-independent).
__global__ void __launch_bounds__(256) exact_gather_kernel(const float* __restrict__ z,
                                                           const float* __restrict__ emb,
                                                           float* __restrict__ out) {
    __shared__ float zs[8][D_DIM];
    int w = threadIdx.x >> 5, lane = threadIdx.x & 31;
    int nrow = blockIdx.x * 8 + w;
    float4* zw = (float4*)zs[w];
    const float4* zp = (const float4*)(z + (size_t)nrow * D_DIM);

    int cnt = g_cnt[nrow];
    if (cnt > CAP) cnt = CAP;
    int widx;
    if (cnt == 1) {
        widx = g_cand[(size_t)nrow * CAP];
    } else {
        #pragma unroll
        for (int j = lane; j < 64; j += 32) zw[j] = zp[j];   // stage only if needed
        __syncwarp();
        unsigned long long best = 0xffffffffffffffffull;
        float aR = g_a[nrow];
        for (int c = lane; c < cnt; c += 32) {
            int k = g_cand[(size_t)nrow * CAP + c];
            const float4* e4 = (const float4*)(emb + (size_t)k * D_DIM);
            float m = 0.0f;
            #pragma unroll 8
            for (int j = 0; j < 64; ++j) {
                float4 ev = e4[j];
                float4 zv = zw[j];
                m = __fmaf_rn(zv.x, ev.x, m);
                m = __fmaf_rn(zv.y, ev.y, m);
                m = __fmaf_rn(zv.z, ev.z, m);
                m = __fmaf_rn(zv.w, ev.w, m);
            }
            float q = __fadd_rn(__fadd_rn(aR, -__fmul_rn(2.0f, m)), g_c[k]);
            unsigned long long v =
                ((unsigned long long)(uint32_t)__float_as_int(q) << 32) | (uint32_t)k;
            best = min(best, v);
        }
        #pragma unroll
        for (int o = 16; o > 0; o >>= 1) {
            unsigned long long v = __shfl_xor_sync(0xffffffffu, best, o);
            best = min(best, v);
        }
        widx = (int)(best & 0xffffffffu);
    }
    if (lane == 0) out[(size_t)N_ROWS * D_DIM + nrow] = (float)widx;

    const float4* eg = (const float4*)(emb + (size_t)widx * D_DIM);
    float4* og = (float4*)(out + (size_t)nrow * D_DIM);
    double s = 0.0;
    #pragma unroll
    for (int j = lane; j < 64; j += 32) {
        float4 ev = eg[j];
        og[j] = ev;
        float4 zv = zp[j];                 // direct (L1/L2-hot)
        double d0 = (double)ev.x - zv.x, d1 = (double)ev.y - zv.y;
        double d2 = (double)ev.z - zv.z, d3 = (double)ev.w - zv.w;
        s += d0 * d0 + d1 * d1 + d2 * d2 + d3 * d3;
    }
    #pragma unroll
    for (int o = 16; o > 0; o >>= 1) s += __shfl_xor_sync(0xffffffffu, s, o);
    if (lane == 0) g_part[nrow] = s;
}

__global__ void finalize_loss_kernel(float* __restrict__ out) {
    __shared__ double sm[512];
    int t = threadIdx.x;
    double s = 0.0;
    const int chunk = N_ROWS / 512;
    #pragma unroll 4
    for (int j = 0; j < chunk; ++j) s += g_part[t * chunk + j];
    sm[t] = s;
    __syncthreads();
    #pragma unroll
    for (int st = 256; st > 0; st >>= 1) {
        if (t < st) sm[t] += sm[t + st];
        __syncthreads();
    }
    if (t == 0) {
        float m = (float)(sm[0] / (double)((size_t)N_ROWS * D_DIM));
        out[(size_t)N_ROWS * D_DIM + N_ROWS] = __fadd_rn(m, __fmul_rn(0.25f, m));
    }
}

// ---------------------------------------------------------------- launch
extern "C" void kernel_launch(void* const* d_in, const int* in_sizes, int n_in,
                              void* d_out, int out_size) {
    const float* z   = (const float*)d_in[0];
    const float* emb = (const float*)d_in[1];
    float* out = (float*)d_out;

    int8_t* z8; cudaGetSymbolAddress((void**)&z8, g_z8);
    int8_t* e8; cudaGetSymbolAddress((void**)&e8, g_e8);
    int* gcnt;  cudaGetSymbolAddress((void**)&gcnt, g_cnt);
    int* gctr;  cudaGetSymbolAddress((void**)&gctr, g_tile_ctr);

    cudaFuncSetAttribute(vq_gemm_kernel,
                         cudaFuncAttributeMaxDynamicSharedMemorySize, SMEM_TOTAL);

    cudaMemsetAsync(gcnt, 0, N_ROWS * sizeof(int));
    cudaMemsetAsync(gctr, 0, sizeof(int));
    norms_quant_z_kernel<<<N_ROWS / 256, 256>>>(z, z8);
    norms_quant_e_kernel<<<K_CODES / 32, 256>>>(emb, e8);
    vq_gemm_kernel<<<GRID_PERSIST, 256, SMEM_TOTAL>>>();
    exact_gather_kernel<<<N_ROWS / 8, 256>>>(z, emb, out);
    finalize_loss_kernel<<<1, 512>>>(out);
}